// round 9
// baseline (speedup 1.0000x reference)
#include <cuda_runtime.h>
#include <cuda_fp16.h>
#include <cstdint>

// GaussianMixture NLL: N=65536 samples (2D), M=1024 mixtures.  SPARSITY == 0.
// nll = -sum_n log( sum_m exp(wlog_m - qf(n,m)) )
//
// v9: single fused kernel.
//  - Every block redundantly computes all mixture coefficients into smem
//    (in-block log_softmax over w + per-mixture folding) -> no prep kernel,
//    no gmem coeff roundtrip.
//  - SPT=2, 64 samples/block, grid=1024 (~7 CTA/SM, 28 warps/SM) to close the
//    issue-efficiency gap (was 50.8% at 14 warps/SM).
//  - Quadratic in packed f32x2 (2 mixtures/instr), exponential via
//    ex2.approx.f16x2 (1 MUFU op per mixture pair), args biased +8 in log2
//    domain; fp16x2 chunk accumulation (8 pairs) flushed to fp32.
//  - Grid-wide finish: atomicAdd into device accumulator, ticketed last block
//    writes out[0] and resets state for graph replays.

#define M_MIX   1024
#define NPAIR   (M_MIX / 2)      // 512
#define QPAIRS  (NPAIR / 4)      // 128 pairs per warp-quarter
#define TPB     128
#define SPT     2
#define SAMP_PER_BLK  64         // 32 lanes * 2 samples
#define BIAS    8.0f             // log2-domain bias, removed in final log

__device__ float        g_sum   = 0.0f;
__device__ unsigned int g_count = 0u;

typedef unsigned long long ull;

// ---------- packed helpers ----------
__device__ __forceinline__ ull pack2(float a, float b) {
    ull r;
    unsigned int lo = __float_as_uint(a), hi = __float_as_uint(b);
    asm("mov.b64 %0, {%1, %2};" : "=l"(r) : "r"(lo), "r"(hi));
    return r;
}
__device__ __forceinline__ void unpack2(ull v, float& a, float& b) {
    unsigned int lo, hi;
    asm("mov.b64 {%0, %1}, %2;" : "=r"(lo), "=r"(hi) : "l"(v));
    a = __uint_as_float(lo);
    b = __uint_as_float(hi);
}
__device__ __forceinline__ ull fmax2_(ull a, ull b, ull c) {
    ull d; asm("fma.rn.f32x2 %0, %1, %2, %3;" : "=l"(d) : "l"(a), "l"(b), "l"(c)); return d;
}
// packed half2 ex2: one MUFU instruction, two exponentials
__device__ __forceinline__ unsigned int hex2(unsigned int x) {
    unsigned int y; asm("ex2.approx.f16x2 %0, %1;" : "=r"(y) : "r"(x)); return y;
}
__device__ __forceinline__ unsigned int hadd2u(unsigned int a, unsigned int b) {
    unsigned int y; asm("add.rn.f16x2 %0, %1, %2;" : "=r"(y) : "r"(a), "r"(b)); return y;
}
__device__ __forceinline__ unsigned int f2h2(float lo, float hi) {
    unsigned int y;
    asm("cvt.rn.f16x2.f32 %0, %1, %2;" : "=r"(y) : "f"(hi), "f"(lo));
    return y;
}

// ---------- fused kernel ----------
__global__ void __launch_bounds__(TPB, 7) gmm_fused(const float* __restrict__ sample,
                                                    const float* __restrict__ mu,
                                                    const float* __restrict__ sigma_log,
                                                    const float* __restrict__ theta,
                                                    const float* __restrict__ w,
                                                    float* __restrict__ out,
                                                    int N, int nblocks) {
    __shared__ __align__(16) float sp[NPAIR * 12];      // 24 KB coefficients
    __shared__ float rbuf[4];
    __shared__ float s_wmax, s_logZ;
    __shared__ float partial[4][SAMP_PER_BLK];
    __shared__ float warpsum[4];

    const int tid  = threadIdx.x;
    const int lane = tid & 31;
    const int wid  = tid >> 5;

    // ===== in-block prep: log_softmax(w) + coefficient folding =====
    {
        float wv[M_MIX / TPB];                   // 8 values per thread
        float lmax = -1e30f;
        #pragma unroll
        for (int i = 0; i < M_MIX / TPB; ++i) {
            wv[i] = w[tid + i * TPB];
            lmax = fmaxf(lmax, wv[i]);
        }
        #pragma unroll
        for (int o = 16; o > 0; o >>= 1) lmax = fmaxf(lmax, __shfl_xor_sync(~0u, lmax, o));
        if (lane == 0) rbuf[wid] = lmax;
        __syncthreads();
        if (tid == 0)
            s_wmax = fmaxf(fmaxf(rbuf[0], rbuf[1]), fmaxf(rbuf[2], rbuf[3]));
        __syncthreads();
        const float wmax = s_wmax;

        float lsum = 0.0f;
        #pragma unroll
        for (int i = 0; i < M_MIX / TPB; ++i) lsum += __expf(wv[i] - wmax);
        #pragma unroll
        for (int o = 16; o > 0; o >>= 1) lsum += __shfl_xor_sync(~0u, lsum, o);
        if (lane == 0) rbuf[wid] = lsum;
        __syncthreads();
        if (tid == 0)
            s_logZ = wmax + __logf(rbuf[0] + rbuf[1] + rbuf[2] + rbuf[3]);
        __syncthreads();
        const float logZ = s_logZ;

        const float L2E = 1.4426950408889634f;
        #pragma unroll
        for (int i = 0; i < M_MIX / TPB; ++i) {
            const int m = tid + i * TPB;
            const float2 sl = ((const float2*)sigma_log)[m];
            const float2 mv = ((const float2*)mu)[m];
            const float a = __expf(-2.0f * sl.x);
            const float b = __expf(-2.0f * sl.y);
            float s, c;
            __sincosf(theta[m], &s, &c);

            const float g11 = a * c * c + b * s * s;
            const float g12 = (a - b) * c * s;
            const float g22 = a * s * s + b * c * c;
            const float wlog = wv[i] - logZ - sl.x - sl.y;

            const float mx = mv.x, my = mv.y;

            const float c0 = -L2E * g11;
            const float c1 = -L2E * 2.0f * g12;
            const float c2 = -L2E * g22;
            const float c3 =  L2E * 2.0f * (g11 * mx + g12 * my);
            const float c4 =  L2E * 2.0f * (g12 * mx + g22 * my);
            const float c5 =  L2E * (wlog - (g11 * mx * mx + 2.0f * g12 * mx * my + g22 * my * my))
                           + BIAS;

            const int j = m >> 1;
            const int l = m & 1;
            float* P = &sp[j * 12];
            P[0  + l] = c0;
            P[2  + l] = c1;
            P[4  + l] = c2;
            P[6  + l] = c3;
            P[8  + l] = c4;
            P[10 + l] = c5;
        }
    }
    __syncthreads();

    // ===== hot loop: warp q handles mixture-quarter q, SPT samples/thread =====
    const int q    = wid;
    const int base = blockIdx.x * SAMP_PER_BLK;

    ull xxp[SPT], xyp[SPT], yyp[SPT], xp[SPT], yp[SPT];
    float accF[SPT];
    #pragma unroll
    for (int k = 0; k < SPT; ++k) {
        const int idx = base + k * 32 + lane;   // coalesced per k
        float x = 0.0f, y = 0.0f;
        if (idx < N) {
            const float2 sv = ((const float2*)sample)[idx];
            x = sv.x; y = sv.y;
        }
        const float xx = x * x, xy = x * y, yy = y * y;
        xxp[k] = pack2(xx, xx);
        xyp[k] = pack2(xy, xy);
        yyp[k] = pack2(yy, yy);
        xp[k]  = pack2(x, x);
        yp[k]  = pack2(y, y);
        accF[k] = 0.0f;
    }

    const float* qp = sp + q * QPAIRS * 12;

    // 16 chunks of 8 pairs; fp16x2 accumulate within a chunk, fp32 flush after
    for (int jc = 0; jc < QPAIRS; jc += 8) {
        unsigned int acch[SPT];
        #pragma unroll
        for (int k = 0; k < SPT; ++k) acch[k] = 0u;

        #pragma unroll
        for (int jj = 0; jj < 8; ++jj) {
            const ulonglong2* bp = (const ulonglong2*)(qp + (jc + jj) * 12);
            const ulonglong2 q0 = bp[0];   // {c0_pair, c1_pair}
            const ulonglong2 q1 = bp[1];   // {c2_pair, c3_pair}
            const ulonglong2 q2 = bp[2];   // {c4_pair, c5_pair}

            #pragma unroll
            for (int k = 0; k < SPT; ++k) {
                ull t = fmax2_(q2.x, yp[k],  q2.y);   // c4*y  + c5(+BIAS)
                t     = fmax2_(q1.y, xp[k],  t);      // +c3*x
                t     = fmax2_(q1.x, yyp[k], t);      // +c2*y^2
                t     = fmax2_(q0.y, xyp[k], t);      // +c1*xy
                t     = fmax2_(q0.x, xxp[k], t);      // +c0*x^2
                float a0, a1;
                unpack2(t, a0, a1);
                acch[k] = hadd2u(acch[k], hex2(f2h2(a0, a1)));
            }
        }

        #pragma unroll
        for (int k = 0; k < SPT; ++k) {
            const __half2 h = *(__half2*)&acch[k];
            const float2  f = __half22float2(h);
            accF[k] += f.x + f.y;
        }
    }

    #pragma unroll
    for (int k = 0; k < SPT; ++k)
        partial[q][k * 32 + lane] = accF[k];
    __syncthreads();

    // combine quarters; one sample per thread (tid < 64)
    float nll_i = 0.0f;
    if (tid < SAMP_PER_BLK) {
        const int sidx = base + tid;
        if (sidx < N) {
            const float tot = partial[0][tid] + partial[1][tid]
                            + partial[2][tid] + partial[3][tid];
            // tot = 2^BIAS * true_sum
            nll_i = 0.69314718055994531f * (BIAS - __log2f(tot));
        }
    }

    // block reduce
    #pragma unroll
    for (int o = 16; o > 0; o >>= 1)
        nll_i += __shfl_xor_sync(0xffffffffu, nll_i, o);
    if (lane == 0) warpsum[wid] = nll_i;
    __syncthreads();

    // grid finish: accumulate, last block publishes + resets for next replay
    if (tid == 0) {
        atomicAdd(&g_sum, warpsum[0] + warpsum[1] + warpsum[2] + warpsum[3]);
        __threadfence();
        const unsigned int ticket = atomicAdd(&g_count, 1u);
        if (ticket == (unsigned int)nblocks - 1u) {
            __threadfence();
            out[0]  = g_sum;
            g_sum   = 0.0f;
            g_count = 0u;
        }
    }
}

extern "C" void kernel_launch(void* const* d_in, const int* in_sizes, int n_in,
                              void* d_out, int out_size) {
    const float* sample    = (const float*)d_in[0];
    const float* mu        = (const float*)d_in[1];
    const float* sigma_log = (const float*)d_in[2];
    const float* theta     = (const float*)d_in[3];
    const float* w         = (const float*)d_in[4];
    float* out = (float*)d_out;

    const int N = in_sizes[0] / 2;
    const int grid = (N + SAMP_PER_BLK - 1) / SAMP_PER_BLK;

    gmm_fused<<<grid, TPB>>>(sample, mu, sigma_log, theta, w, out, N, grid);
}

// round 11
// speedup vs baseline: 1.6050x; 1.6050x over previous
#include <cuda_runtime.h>
#include <cuda_fp16.h>
#include <cstdint>

// GaussianMixture NLL: N=65536 samples (2D), M=1024 mixtures.  SPARSITY == 0.
// nll = -sum_n log( sum_m exp(wlog_m - qf(n,m)) )
//
// v10: two-kernel (fusion reverted — R9 regressed). Hot loop entirely in
//  fp16x2 — NO fp32->fp16 cvt in the loop (cvt shared the MUFU/XU pipe):
//    poly'(n,m) = c0*xx + c1*xy + c2*yy + c3*x + c4*y     (fp16x2, 2 mixtures)
//    acc += w_m * 2^poly'          w_m = 2^(c5+BIAS) as multiplicative fp16
//  Ranges: poly' in [-6,+3], e<=8, w<=4 -> no fp16 overflow; chunk-of-8
//  accumulation flushed to fp32 (same scheme R8 validated at 3.3e-4).
//  TPB=256: 8 warps = 8 mixture-eighths (64 pairs), SPT=4 -> grid=512,
//  ~28 warps/SM, regs capped at 64.

#define M_MIX   1024
#define NPAIR   (M_MIX / 2)      // 512
#define EPAIRS  (NPAIR / 8)      // 64 pairs per warp-eighth
#define TPB     256
#define SPT     4
#define SAMP_PER_BLK  128        // 32 lanes * 4 samples
#define BIAS    8.0f             // log2-domain bias folded into w

// pair records: {c0,c1,c2,c3} {c4,w,pad,pad} as half2 words -> 32B/pair
__device__ uint4 g_params[NPAIR * 2];

// ---------- helpers ----------
__device__ __forceinline__ __half2 u2h2(unsigned int u) {
    __half2 h; *(unsigned int*)&h = u; return h;
}
__device__ __forceinline__ unsigned int h2u(__half2 h) {
    return *(unsigned int*)&h;
}
__device__ __forceinline__ __half2 hex2(__half2 x) {
    unsigned int y;
    asm("ex2.approx.f16x2 %0, %1;" : "=r"(y) : "r"(h2u(x)));
    return u2h2(y);
}

// ---------- prep: log_softmax(w) + fp16 coefficient records ----------
__global__ void gmm_prep(const float* __restrict__ mu,
                         const float* __restrict__ sigma_log,
                         const float* __restrict__ theta,
                         const float* __restrict__ w,
                         float* __restrict__ out) {
    __shared__ float red[32];
    __shared__ float stage[6][M_MIX];     // scalar c0..c4, w per mixture
    const int m    = threadIdx.x;
    const int lane = m & 31;
    const int wid  = m >> 5;

    const float wi = w[m];

    // block max via shuffle
    float v = wi;
    #pragma unroll
    for (int o = 16; o > 0; o >>= 1) v = fmaxf(v, __shfl_xor_sync(~0u, v, o));
    if (lane == 0) red[wid] = v;
    __syncthreads();
    float wmax = red[lane & 31];
    #pragma unroll
    for (int o = 16; o > 0; o >>= 1) wmax = fmaxf(wmax, __shfl_xor_sync(~0u, wmax, o));
    wmax = __shfl_sync(~0u, wmax, 0);
    __syncthreads();

    // block sum(exp) via shuffle
    float e = __expf(wi - wmax);
    #pragma unroll
    for (int o = 16; o > 0; o >>= 1) e += __shfl_xor_sync(~0u, e, o);
    if (lane == 0) red[wid] = e;
    __syncthreads();
    float esum = red[lane & 31];
    #pragma unroll
    for (int o = 16; o > 0; o >>= 1) esum += __shfl_xor_sync(~0u, esum, o);
    esum = __shfl_sync(~0u, esum, 0);

    const float logZ = wmax + __logf(esum);

    const float sl0 = sigma_log[2 * m + 0];
    const float sl1 = sigma_log[2 * m + 1];
    const float a = __expf(-2.0f * sl0);
    const float b = __expf(-2.0f * sl1);
    float s, c;
    __sincosf(theta[m], &s, &c);

    const float g11 = a * c * c + b * s * s;
    const float g12 = (a - b) * c * s;
    const float g22 = a * s * s + b * c * c;
    const float wlog = wi - logZ - sl0 - sl1;

    const float mx = mu[2 * m + 0];
    const float my = mu[2 * m + 1];

    const float L2E = 1.4426950408889634f;

    const float qmu = g11 * mx * mx + 2.0f * g12 * mx * my + g22 * my * my;

    stage[0][m] = -L2E * g11;                          // c0
    stage[1][m] = -L2E * 2.0f * g12;                   // c1
    stage[2][m] = -L2E * g22;                          // c2
    stage[3][m] =  L2E * 2.0f * (g11 * mx + g12 * my); // c3
    stage[4][m] =  L2E * 2.0f * (g12 * mx + g22 * my); // c4
    stage[5][m] = exp2f(L2E * (wlog - qmu) + BIAS);    // w = 2^(c5+BIAS)
    __syncthreads();

    // pack pair records (threads 0..511)
    if (m < NPAIR) {
        const int m0 = 2 * m, m1 = 2 * m + 1;
        uint4 r0, r1;
        r0.x = h2u(__floats2half2_rn(stage[0][m0], stage[0][m1]));
        r0.y = h2u(__floats2half2_rn(stage[1][m0], stage[1][m1]));
        r0.z = h2u(__floats2half2_rn(stage[2][m0], stage[2][m1]));
        r0.w = h2u(__floats2half2_rn(stage[3][m0], stage[3][m1]));
        r1.x = h2u(__floats2half2_rn(stage[4][m0], stage[4][m1]));
        r1.y = h2u(__floats2half2_rn(stage[5][m0], stage[5][m1]));
        r1.z = 0u; r1.w = 0u;
        g_params[2 * m + 0] = r0;
        g_params[2 * m + 1] = r1;
    }

    if (m == 0) out[0] = 0.0f;        // re-zeroed every replay -> deterministic
}

// ---------- hot loop ----------
__global__ void __launch_bounds__(TPB, 4) gmm_main(const float* __restrict__ sample,
                                                   float* __restrict__ out,
                                                   int N) {
    __shared__ __align__(16) uint4 sp[NPAIR * 2];      // 16 KB coefficient records
    __shared__ float partial[8][SAMP_PER_BLK];
    __shared__ float warpsum[8];

    const int tid  = threadIdx.x;
    const int lane = tid & 31;
    const int wid  = tid >> 3 >> 2;                    // tid >> 5

    // cooperative param load (1024 uint4)
    #pragma unroll
    for (int i = tid; i < NPAIR * 2; i += TPB) sp[i] = g_params[i];
    __syncthreads();

    const int base = blockIdx.x * SAMP_PER_BLK;

    // per-sample fp16x2 monomials (value broadcast to both lanes)
    __half2 hxx[SPT], hxy[SPT], hyy[SPT], hx[SPT], hy[SPT];
    __half2 acch[SPT];
    float accF[SPT];
    #pragma unroll
    for (int k = 0; k < SPT; ++k) {
        const int idx = base + k * 32 + lane;   // coalesced per k
        float x = 0.0f, y = 0.0f;
        if (idx < N) {
            const float2 sv = ((const float2*)sample)[idx];
            x = sv.x; y = sv.y;
        }
        hxx[k] = __float2half2_rn(x * x);
        hxy[k] = __float2half2_rn(x * y);
        hyy[k] = __float2half2_rn(y * y);
        hx[k]  = __float2half2_rn(x);
        hy[k]  = __float2half2_rn(y);
        accF[k] = 0.0f;
    }

    const uint4* ep = sp + wid * EPAIRS * 2;   // this warp's eighth

    // 8 chunks of 8 pairs; fp16x2 accumulate within a chunk, fp32 flush after
    for (int jc = 0; jc < EPAIRS; jc += 8) {
        #pragma unroll
        for (int k = 0; k < SPT; ++k) acch[k] = u2h2(0u);

        #pragma unroll
        for (int jj = 0; jj < 8; ++jj) {
            const uint4 r0 = ep[(jc + jj) * 2 + 0];
            const uint4 r1 = ep[(jc + jj) * 2 + 1];
            const __half2 C0 = u2h2(r0.x), C1 = u2h2(r0.y);
            const __half2 C2 = u2h2(r0.z), C3 = u2h2(r0.w);
            const __half2 C4 = u2h2(r1.x), W  = u2h2(r1.y);

            #pragma unroll
            for (int k = 0; k < SPT; ++k) {
                __half2 p = __hmul2(C0, hxx[k]);
                p = __hfma2(C1, hxy[k], p);
                p = __hfma2(C2, hyy[k], p);
                p = __hfma2(C3, hx[k],  p);
                p = __hfma2(C4, hy[k],  p);        // poly' in [-6,+3]
                acch[k] = __hfma2(W, hex2(p), acch[k]);
            }
        }

        #pragma unroll
        for (int k = 0; k < SPT; ++k) {
            const float2 f = __half22float2(acch[k]);
            accF[k] += f.x + f.y;
        }
    }

    #pragma unroll
    for (int k = 0; k < SPT; ++k)
        partial[wid][k * 32 + lane] = accF[k];
    __syncthreads();

    // combine eighths; one sample per thread (tid < 128)
    float nll_i = 0.0f;
    if (tid < SAMP_PER_BLK) {
        const int sidx = base + tid;
        if (sidx < N) {
            float tot = 0.0f;
            #pragma unroll
            for (int q = 0; q < 8; ++q) tot += partial[q][tid];
            // tot = 2^BIAS * true_sum
            nll_i = 0.69314718055994531f * (BIAS - __log2f(tot));
        }
    }

    // block reduce
    #pragma unroll
    for (int o = 16; o > 0; o >>= 1)
        nll_i += __shfl_xor_sync(0xffffffffu, nll_i, o);
    if (lane == 0) warpsum[wid] = nll_i;
    __syncthreads();

    if (tid == 0) {
        float v = 0.0f;
        #pragma unroll
        for (int i = 0; i < 8; ++i) v += warpsum[i];
        atomicAdd(out, v);
    }
}

extern "C" void kernel_launch(void* const* d_in, const int* in_sizes, int n_in,
                              void* d_out, int out_size) {
    const float* sample    = (const float*)d_in[0];
    const float* mu        = (const float*)d_in[1];
    const float* sigma_log = (const float*)d_in[2];
    const float* theta     = (const float*)d_in[3];
    const float* w         = (const float*)d_in[4];
    float* out = (float*)d_out;

    const int N = in_sizes[0] / 2;
    const int grid = (N + SAMP_PER_BLK - 1) / SAMP_PER_BLK;

    gmm_prep<<<1, M_MIX>>>(mu, sigma_log, theta, w, out);
    gmm_main<<<grid, TPB>>>(sample, out, N);
}